// round 2
// baseline (speedup 1.0000x reference)
#include <cuda_runtime.h>

#define NN 10000
#define EE 640000
#define TRI_N 49995000   // N*(N-1)/2
#define NEG_SLOPE 0.01f

// Scratch (no allocations allowed in kernel_launch)
__device__ float g_ef[3 * EE];   // planar edge features: g_ef[k*EE + e]
__device__ float g_agg[NN * 3];  // per-layer aggregation buffer
__device__ float g_x1[NN * 3];   // ping
__device__ float g_x2[NN * 3];   // pong

// ---------------------------------------------------------------------------
// Prep: gather edge features (layer-invariant) + zero agg
// ---------------------------------------------------------------------------
__global__ void prep_kernel(const float* __restrict__ edge_embeds,
                            const int* __restrict__ edge_index) {
    int e = blockIdx.x * blockDim.x + threadIdx.x;
    if (e < NN * 3) g_agg[e] = 0.0f;
    if (e >= EE) return;

    int2 st = ((const int2*)edge_index)[e];
    int a = min(st.x, st.y);
    int b = max(st.x, st.y);
    // tri = a*N - a*(a+3)/2 + b - 1   (fits in int32; a*(a+3) is always even)
    int tri = a * NN - (a * (a + 3)) / 2 + b - 1;
    if (tri < 0) tri += TRI_N;  // JAX wraps negative index (a==b==0 case)

    const float* ef = edge_embeds + (long long)tri * 3;
    g_ef[e]          = ef[0];
    g_ef[EE + e]     = ef[1];
    g_ef[2 * EE + e] = ef[2];
}

// ---------------------------------------------------------------------------
// Edge pass: msg = relu(x[src] + ef), atomic scatter-sum into agg[tgt]
// x_sel: 0 = node_embeds param, 1 = g_x1, 2 = g_x2
// ---------------------------------------------------------------------------
__global__ void edge_kernel(int x_sel, const float* __restrict__ node_embeds,
                            const int* __restrict__ edge_index) {
    int e = blockIdx.x * blockDim.x + threadIdx.x;
    if (e >= EE) return;

    const float* x = (x_sel == 0) ? node_embeds : (x_sel == 1 ? g_x1 : g_x2);

    int2 st = ((const int2*)edge_index)[e];
    int s = st.x, t = st.y;

    float x0 = x[3 * s + 0];
    float x1 = x[3 * s + 1];
    float x2 = x[3 * s + 2];

    float m0 = fmaxf(x0 + g_ef[e], 0.0f);
    float m1 = fmaxf(x1 + g_ef[EE + e], 0.0f);
    float m2 = fmaxf(x2 + g_ef[2 * EE + e], 0.0f);

    atomicAdd(&g_agg[3 * t + 0], m0);
    atomicAdd(&g_agg[3 * t + 1], m1);
    atomicAdd(&g_agg[3 * t + 2], m2);
}

// ---------------------------------------------------------------------------
// Node MLP: h = concat(agg, x); 4 tiny linear layers; also re-zero agg.
// in_sel:  0 = node_embeds, 1 = g_x1, 2 = g_x2
// out_sel: 0 = d_out,       1 = g_x1, 2 = g_x2
// ---------------------------------------------------------------------------
__device__ __forceinline__ float leaky(float v) {
    return v >= 0.0f ? v : NEG_SLOPE * v;
}

__global__ void node_kernel(int in_sel, int out_sel,
                            const float* __restrict__ node_embeds,
                            float* __restrict__ d_out,
                            const float* __restrict__ W1, const float* __restrict__ b1,
                            const float* __restrict__ W2, const float* __restrict__ b2,
                            const float* __restrict__ W3, const float* __restrict__ b3,
                            const float* __restrict__ W4, const float* __restrict__ b4,
                            int layer) {
    __shared__ float sW1[36], sb1[6], sW2[36], sb2[6], sW3[18], sb3[3], sW4[9], sb4[3];
    int tid = threadIdx.x;
    if (tid < 36) { sW1[tid] = W1[layer * 36 + tid]; sW2[tid] = W2[layer * 36 + tid]; }
    if (tid < 18) { sW3[tid] = W3[layer * 18 + tid]; }
    if (tid < 9)  { sW4[tid] = W4[layer * 9 + tid]; }
    if (tid < 6)  { sb1[tid] = b1[layer * 6 + tid]; sb2[tid] = b2[layer * 6 + tid]; }
    if (tid < 3)  { sb3[tid] = b3[layer * 3 + tid]; sb4[tid] = b4[layer * 3 + tid]; }
    __syncthreads();

    int i = blockIdx.x * blockDim.x + tid;
    if (i >= NN) return;

    const float* x = (in_sel == 0) ? node_embeds : (in_sel == 1 ? g_x1 : g_x2);
    float* xo = (out_sel == 0) ? d_out : (out_sel == 1 ? g_x1 : g_x2);

    float h[6];
    h[0] = g_agg[3 * i + 0];
    h[1] = g_agg[3 * i + 1];
    h[2] = g_agg[3 * i + 2];
    h[3] = x[3 * i + 0];
    h[4] = x[3 * i + 1];
    h[5] = x[3 * i + 2];

    // re-zero agg for the next layer / next replay
    g_agg[3 * i + 0] = 0.0f;
    g_agg[3 * i + 1] = 0.0f;
    g_agg[3 * i + 2] = 0.0f;

    float t1[6], t2[6], t3[3];
#pragma unroll
    for (int j = 0; j < 6; j++) {
        float acc = sb1[j];
#pragma unroll
        for (int k = 0; k < 6; k++) acc = fmaf(h[k], sW1[k * 6 + j], acc);
        t1[j] = leaky(acc);
    }
#pragma unroll
    for (int j = 0; j < 6; j++) {
        float acc = sb2[j];
#pragma unroll
        for (int k = 0; k < 6; k++) acc = fmaf(t1[k], sW2[k * 6 + j], acc);
        t2[j] = leaky(acc);
    }
#pragma unroll
    for (int j = 0; j < 3; j++) {
        float acc = sb3[j];
#pragma unroll
        for (int k = 0; k < 6; k++) acc = fmaf(t2[k], sW3[k * 3 + j], acc);
        t3[j] = leaky(acc);
    }
#pragma unroll
    for (int j = 0; j < 3; j++) {
        float acc = sb4[j];
#pragma unroll
        for (int k = 0; k < 3; k++) acc = fmaf(t3[k], sW4[k * 3 + j], acc);
        xo[3 * i + j] = acc;
    }
}

// ---------------------------------------------------------------------------
// kernel_launch
// ---------------------------------------------------------------------------
extern "C" void kernel_launch(void* const* d_in, const int* in_sizes, int n_in,
                              void* d_out, int out_size) {
    const float* node_embeds = (const float*)d_in[0];
    const float* edge_embeds = (const float*)d_in[1];
    const int*   edge_index  = (const int*)d_in[2];
    const float* W1 = (const float*)d_in[3];
    const float* b1 = (const float*)d_in[4];
    const float* W2 = (const float*)d_in[5];
    const float* b2 = (const float*)d_in[6];
    const float* W3 = (const float*)d_in[7];
    const float* b3 = (const float*)d_in[8];
    const float* W4 = (const float*)d_in[9];
    const float* b4 = (const float*)d_in[10];
    float* out = (float*)d_out;

    const int EB = 256;
    const int egrid = (EE + EB - 1) / EB;
    const int NB = 256;
    const int ngrid = (NN + NB - 1) / NB;

    prep_kernel<<<egrid, EB>>>(edge_embeds, edge_index);

    // layer 0: x = node_embeds -> g_x1
    edge_kernel<<<egrid, EB>>>(0, node_embeds, edge_index);
    node_kernel<<<ngrid, NB>>>(0, 1, node_embeds, out,
                               W1, b1, W2, b2, W3, b3, W4, b4, 0);
    // layer 1: g_x1 -> g_x2
    edge_kernel<<<egrid, EB>>>(1, node_embeds, edge_index);
    node_kernel<<<ngrid, NB>>>(1, 2, node_embeds, out,
                               W1, b1, W2, b2, W3, b3, W4, b4, 1);
    // layer 2: g_x2 -> d_out
    edge_kernel<<<egrid, EB>>>(2, node_embeds, edge_index);
    node_kernel<<<ngrid, NB>>>(2, 0, node_embeds, out,
                               W1, b1, W2, b2, W3, b3, W4, b4, 2);
}

// round 3
// speedup vs baseline: 1.3200x; 1.3200x over previous
#include <cuda_runtime.h>

#define NN 10000
#define EE 640000
#define TRI_N 49995000   // N*(N-1)/2
#define NEG_SLOPE 0.01f
#define SCAN_T 1024
#define CHUNK 10         // ceil(NN / SCAN_T)

// ---------------------------------------------------------------------------
// Scratch (device globals; BSS zero-initialized at load, so g_cnt starts 0)
// ---------------------------------------------------------------------------
__device__ int    g_cnt[NN];       // per-target running counters
__device__ int    g_row[NN + 1];   // CSR row pointers
__device__ float4 g_edge[EE];      // CSR edges: (ef0, ef1, ef2, src-as-float-bits)
__device__ float  g_x1[NN * 3];    // ping
__device__ float  g_x2[NN * 3];    // pong

// ---------------------------------------------------------------------------
// 1) Histogram of targets
// ---------------------------------------------------------------------------
__global__ void hist_kernel(const int* __restrict__ edge_index) {
    int e = blockIdx.x * blockDim.x + threadIdx.x;
    if (e >= EE) return;
    int2 st = ((const int2*)edge_index)[e];
    atomicAdd(&g_cnt[st.y], 1);
}

// ---------------------------------------------------------------------------
// 2) Exclusive prefix scan over the 10k counters -> g_row; zero counters
//    (single block, Hillis-Steele over 1024 partials)
// ---------------------------------------------------------------------------
__global__ void scan_kernel() {
    __shared__ int sp[SCAN_T];
    int tid = threadIdx.x;
    int beg = tid * CHUNK;
    int end = min(beg + CHUNK, NN);

    int local[CHUNK];
    int sum = 0;
    for (int k = beg; k < end; k++) {
        int v = g_cnt[k];
        local[k - beg] = v;
        sum += v;
    }
    sp[tid] = sum;
    __syncthreads();

    for (int off = 1; off < SCAN_T; off <<= 1) {
        int v = (tid >= off) ? sp[tid - off] : 0;
        __syncthreads();
        sp[tid] += v;
        __syncthreads();
    }

    int run = (tid == 0) ? 0 : sp[tid - 1];  // exclusive
    for (int k = beg; k < end; k++) {
        g_row[k] = run;
        run += local[k - beg];
        g_cnt[k] = 0;                        // ready for scatter
    }
    if (tid == 0) g_row[NN] = EE;
}

// ---------------------------------------------------------------------------
// 3) Scatter: gather edge features from the 600MB triangular array (the one
//    unavoidable random-access pass) and place edges in CSR order.
// ---------------------------------------------------------------------------
__global__ void scatter_kernel(const float* __restrict__ edge_embeds,
                               const int* __restrict__ edge_index) {
    int e = blockIdx.x * blockDim.x + threadIdx.x;
    if (e >= EE) return;

    int2 st = ((const int2*)edge_index)[e];
    int s = st.x, t = st.y;
    int a = min(s, t), b = max(s, t);
    int tri = a * NN - (a * (a + 3)) / 2 + b - 1;
    if (tri < 0) tri += TRI_N;               // JAX wraps index -1 (a==b==0)

    const float* ef = edge_embeds + (long long)tri * 3;
    float e0 = ef[0], e1 = ef[1], e2 = ef[2];

    int pos = g_row[t] + atomicAdd(&g_cnt[t], 1);
    g_edge[pos] = make_float4(e0, e1, e2, __int_as_float(s));
}

// ---------------------------------------------------------------------------
// 4) Fused layer: per-node warp reduction over its CSR segment (no atomics),
//    then the 4-layer MLP on lane 0. layer 0 also re-zeros g_cnt for next replay.
// ---------------------------------------------------------------------------
__device__ __forceinline__ float leaky(float v) {
    return v >= 0.0f ? v : NEG_SLOPE * v;
}

__global__ void layer_kernel(int in_sel, int out_sel,
                             const float* __restrict__ node_embeds,
                             float* __restrict__ d_out,
                             const float* __restrict__ W1, const float* __restrict__ b1,
                             const float* __restrict__ W2, const float* __restrict__ b2,
                             const float* __restrict__ W3, const float* __restrict__ b3,
                             const float* __restrict__ W4, const float* __restrict__ b4,
                             int layer) {
    __shared__ float sW1[36], sb1[6], sW2[36], sb2[6], sW3[18], sb3[3], sW4[9], sb4[3];
    int tid = threadIdx.x;
    if (tid < 36) { sW1[tid] = W1[layer * 36 + tid]; sW2[tid] = W2[layer * 36 + tid]; }
    if (tid < 18) { sW3[tid] = W3[layer * 18 + tid]; }
    if (tid < 9)  { sW4[tid] = W4[layer * 9 + tid]; }
    if (tid < 6)  { sb1[tid] = b1[layer * 6 + tid]; sb2[tid] = b2[layer * 6 + tid]; }
    if (tid < 3)  { sb3[tid] = b3[layer * 3 + tid]; sb4[tid] = b4[layer * 3 + tid]; }
    __syncthreads();

    int wid  = tid >> 5;
    int lane = tid & 31;
    int i = blockIdx.x * 8 + wid;            // 8 warps/block, one node per warp
    if (i >= NN) return;

    const float* x = (in_sel == 0) ? node_embeds : (in_sel == 1 ? g_x1 : g_x2);

    int s0 = g_row[i], s1 = g_row[i + 1];
    float a0 = 0.0f, a1 = 0.0f, a2 = 0.0f;
    for (int j = s0 + lane; j < s1; j += 32) {
        float4 v = g_edge[j];
        int s = __float_as_int(v.w);
        const float* xs = x + 3 * s;
        a0 += fmaxf(xs[0] + v.x, 0.0f);
        a1 += fmaxf(xs[1] + v.y, 0.0f);
        a2 += fmaxf(xs[2] + v.z, 0.0f);
    }
#pragma unroll
    for (int off = 16; off > 0; off >>= 1) {
        a0 += __shfl_down_sync(0xFFFFFFFF, a0, off);
        a1 += __shfl_down_sync(0xFFFFFFFF, a1, off);
        a2 += __shfl_down_sync(0xFFFFFFFF, a2, off);
    }

    if (lane == 0) {
        if (layer == 0) g_cnt[i] = 0;        // reset counters for next replay

        float* xo = (out_sel == 0) ? d_out : (out_sel == 1 ? g_x1 : g_x2);

        float h[6];
        h[0] = a0; h[1] = a1; h[2] = a2;
        h[3] = x[3 * i + 0];
        h[4] = x[3 * i + 1];
        h[5] = x[3 * i + 2];

        float t1[6], t2[6], t3[3];
#pragma unroll
        for (int j = 0; j < 6; j++) {
            float acc = sb1[j];
#pragma unroll
            for (int k = 0; k < 6; k++) acc = fmaf(h[k], sW1[k * 6 + j], acc);
            t1[j] = leaky(acc);
        }
#pragma unroll
        for (int j = 0; j < 6; j++) {
            float acc = sb2[j];
#pragma unroll
            for (int k = 0; k < 6; k++) acc = fmaf(t1[k], sW2[k * 6 + j], acc);
            t2[j] = leaky(acc);
        }
#pragma unroll
        for (int j = 0; j < 3; j++) {
            float acc = sb3[j];
#pragma unroll
            for (int k = 0; k < 6; k++) acc = fmaf(t2[k], sW3[k * 3 + j], acc);
            t3[j] = leaky(acc);
        }
#pragma unroll
        for (int j = 0; j < 3; j++) {
            float acc = sb4[j];
#pragma unroll
            for (int k = 0; k < 3; k++) acc = fmaf(t3[k], sW4[k * 3 + j], acc);
            xo[3 * i + j] = acc;
        }
    }
}

// ---------------------------------------------------------------------------
// kernel_launch
// ---------------------------------------------------------------------------
extern "C" void kernel_launch(void* const* d_in, const int* in_sizes, int n_in,
                              void* d_out, int out_size) {
    const float* node_embeds = (const float*)d_in[0];
    const float* edge_embeds = (const float*)d_in[1];
    const int*   edge_index  = (const int*)d_in[2];
    const float* W1 = (const float*)d_in[3];
    const float* b1 = (const float*)d_in[4];
    const float* W2 = (const float*)d_in[5];
    const float* b2 = (const float*)d_in[6];
    const float* W3 = (const float*)d_in[7];
    const float* b3 = (const float*)d_in[8];
    const float* W4 = (const float*)d_in[9];
    const float* b4 = (const float*)d_in[10];
    float* out = (float*)d_out;

    const int EB = 256;
    const int egrid = (EE + EB - 1) / EB;
    const int lgrid = (NN + 7) / 8;          // 8 nodes (warps) per 256-thread block

    hist_kernel<<<egrid, EB>>>(edge_index);
    scan_kernel<<<1, SCAN_T>>>();
    scatter_kernel<<<egrid, EB>>>(edge_embeds, edge_index);

    layer_kernel<<<lgrid, 256>>>(0, 1, node_embeds, out,
                                 W1, b1, W2, b2, W3, b3, W4, b4, 0);
    layer_kernel<<<lgrid, 256>>>(1, 2, node_embeds, out,
                                 W1, b1, W2, b2, W3, b3, W4, b4, 1);
    layer_kernel<<<lgrid, 256>>>(2, 0, node_embeds, out,
                                 W1, b1, W2, b2, W3, b3, W4, b4, 2);
}

// round 6
// speedup vs baseline: 1.3409x; 1.0159x over previous
#include <cuda_runtime.h>

#define NN 10000
#define EE 640000
#define TRI_N 49995000   // N*(N-1)/2
#define NEG_SLOPE 0.01f
#define SCAN_T 1024
#define CHUNK 10         // ceil(NN / SCAN_T)

// ---------------------------------------------------------------------------
// Scratch (device globals; BSS zero-initialized at load, so g_cnt starts 0)
// ---------------------------------------------------------------------------
__device__ int    g_cnt[NN];       // per-target running counters
__device__ int    g_row[NN + 1];   // CSR row pointers
__device__ float4 g_edge[EE];      // CSR edges: (ef0, ef1, ef2, src-as-float-bits)
__device__ float4 g_xa[NN];        // x ping (padded to 16B for 1-load gather)
__device__ float4 g_xb[NN];        // x pong

// ---------------------------------------------------------------------------
// 1) Histogram of targets (2 edges/thread via int4) + convert node_embeds
//    to float4 layout for single-LDG.128 gathers in the layer kernels.
// ---------------------------------------------------------------------------
__global__ void __launch_bounds__(256) hist_kernel(const int* __restrict__ edge_index,
                                                   const float* __restrict__ node_embeds) {
    int t = blockIdx.x * blockDim.x + threadIdx.x;

    if (t < NN) {
        const float* p = node_embeds + 3 * t;
        g_xa[t] = make_float4(p[0], p[1], p[2], 0.0f);
    }

    if (2 * t >= EE) return;
    int4 q = ((const int4*)edge_index)[t];   // edges 2t and 2t+1
    atomicAdd(&g_cnt[q.y], 1);
    atomicAdd(&g_cnt[q.w], 1);
}

// ---------------------------------------------------------------------------
// 2) Exclusive prefix scan over the 10k counters -> g_row; zero counters
// ---------------------------------------------------------------------------
__global__ void scan_kernel() {
    __shared__ int sp[SCAN_T];
    int tid = threadIdx.x;
    int beg = tid * CHUNK;
    int end = min(beg + CHUNK, NN);

    int local[CHUNK];
    int sum = 0;
    for (int k = beg; k < end; k++) {
        int v = g_cnt[k];
        local[k - beg] = v;
        sum += v;
    }
    sp[tid] = sum;
    __syncthreads();

    for (int off = 1; off < SCAN_T; off <<= 1) {
        int v = (tid >= off) ? sp[tid - off] : 0;
        __syncthreads();
        sp[tid] += v;
        __syncthreads();
    }

    int run = (tid == 0) ? 0 : sp[tid - 1];  // exclusive
    for (int k = beg; k < end; k++) {
        g_row[k] = run;
        run += local[k - beg];
        g_cnt[k] = 0;                        // ready for scatter
    }
    if (tid == 0) g_row[NN] = EE;
}

// ---------------------------------------------------------------------------
// 3) Scatter: 2 edges/thread. Random gather from the 600MB triangular array,
//    place edges in CSR order. Streaming store (no L1 reuse of g_edge here).
// ---------------------------------------------------------------------------
__global__ void __launch_bounds__(256) scatter_kernel(const float* __restrict__ edge_embeds,
                                                      const int* __restrict__ edge_index) {
    int t = blockIdx.x * blockDim.x + threadIdx.x;
    if (2 * t >= EE) return;

    int4 q = ((const int4*)edge_index)[t];
    int sA = q.x, tA = q.y;
    int sB = q.z, tB = q.w;

    int aA = min(sA, tA), bA = max(sA, tA);
    int aB = min(sB, tB), bB = max(sB, tB);
    int triA = aA * NN - (aA * (aA + 3)) / 2 + bA - 1;
    int triB = aB * NN - (aB * (aB + 3)) / 2 + bB - 1;
    if (triA < 0) triA += TRI_N;             // JAX wraps index -1 (a==b==0)
    if (triB < 0) triB += TRI_N;

    const float* pA = edge_embeds + (long long)triA * 3;
    const float* pB = edge_embeds + (long long)triB * 3;
    // 6 independent loads in flight
    float fA0 = __ldg(pA + 0), fA1 = __ldg(pA + 1), fA2 = __ldg(pA + 2);
    float fB0 = __ldg(pB + 0), fB1 = __ldg(pB + 1), fB2 = __ldg(pB + 2);

    int posA = g_row[tA] + atomicAdd(&g_cnt[tA], 1);
    int posB = g_row[tB] + atomicAdd(&g_cnt[tB], 1);
    __stcg(&g_edge[posA], make_float4(fA0, fA1, fA2, __int_as_float(sA)));
    __stcg(&g_edge[posB], make_float4(fB0, fB1, fB2, __int_as_float(sB)));
}

// ---------------------------------------------------------------------------
// 4) Fused layer: warp-per-node, unroll-4 predicated edge loop (no atomics),
//    float4 x-gather, MLP on lane 0. Layer 0 re-zeros g_cnt for next replay.
// ---------------------------------------------------------------------------
__device__ __forceinline__ float leaky(float v) {
    return v >= 0.0f ? v : NEG_SLOPE * v;
}

__global__ void __launch_bounds__(256) layer_kernel(
                             int in_sel, int out_sel,
                             float* __restrict__ d_out,
                             const float* __restrict__ W1, const float* __restrict__ b1,
                             const float* __restrict__ W2, const float* __restrict__ b2,
                             const float* __restrict__ W3, const float* __restrict__ b3,
                             const float* __restrict__ W4, const float* __restrict__ b4,
                             int layer) {
    __shared__ float sW1[36], sb1[6], sW2[36], sb2[6], sW3[18], sb3[3], sW4[9], sb4[3];
    int tid = threadIdx.x;
    if (tid < 36) { sW1[tid] = W1[layer * 36 + tid]; sW2[tid] = W2[layer * 36 + tid]; }
    if (tid < 18) { sW3[tid] = W3[layer * 18 + tid]; }
    if (tid < 9)  { sW4[tid] = W4[layer * 9 + tid]; }
    if (tid < 6)  { sb1[tid] = b1[layer * 6 + tid]; sb2[tid] = b2[layer * 6 + tid]; }
    if (tid < 3)  { sb3[tid] = b3[layer * 3 + tid]; sb4[tid] = b4[layer * 3 + tid]; }
    __syncthreads();

    int wid  = tid >> 5;
    int lane = tid & 31;
    int i = blockIdx.x * 8 + wid;            // 8 warps/block, one node per warp
    if (i >= NN) return;

    const float4* __restrict__ x = in_sel ? g_xb : g_xa;

    int s0 = g_row[i], s1 = g_row[i + 1];
    float a0 = 0.0f, a1 = 0.0f, a2 = 0.0f;

    for (int base = s0; base < s1; base += 128) {
#pragma unroll
        for (int u = 0; u < 4; u++) {
            int j = base + lane + u * 32;
            if (j < s1) {
                float4 v  = __ldg(&g_edge[j]);
                float4 xs = __ldg(&x[__float_as_int(v.w)]);
                a0 += fmaxf(xs.x + v.x, 0.0f);
                a1 += fmaxf(xs.y + v.y, 0.0f);
                a2 += fmaxf(xs.z + v.z, 0.0f);
            }
        }
    }

#pragma unroll
    for (int off = 16; off > 0; off >>= 1) {
        a0 += __shfl_down_sync(0xFFFFFFFF, a0, off);
        a1 += __shfl_down_sync(0xFFFFFFFF, a1, off);
        a2 += __shfl_down_sync(0xFFFFFFFF, a2, off);
    }

    if (lane == 0) {
        if (layer == 0) g_cnt[i] = 0;        // reset counters for next replay

        float4 xi = x[i];
        float h[6];
        h[0] = a0; h[1] = a1; h[2] = a2;
        h[3] = xi.x; h[4] = xi.y; h[5] = xi.z;

        float t1[6], t2[6], t3[3];
#pragma unroll
        for (int j = 0; j < 6; j++) {
            float acc = sb1[j];
#pragma unroll
            for (int k = 0; k < 6; k++) acc = fmaf(h[k], sW1[k * 6 + j], acc);
            t1[j] = leaky(acc);
        }
#pragma unroll
        for (int j = 0; j < 6; j++) {
            float acc = sb2[j];
#pragma unroll
            for (int k = 0; k < 6; k++) acc = fmaf(t1[k], sW2[k * 6 + j], acc);
            t2[j] = leaky(acc);
        }
#pragma unroll
        for (int j = 0; j < 3; j++) {
            float acc = sb3[j];
#pragma unroll
            for (int k = 0; k < 6; k++) acc = fmaf(t2[k], sW3[k * 3 + j], acc);
            t3[j] = leaky(acc);
        }
        float o0, o1, o2;
        {
            float acc0 = sb4[0], acc1 = sb4[1], acc2 = sb4[2];
#pragma unroll
            for (int k = 0; k < 3; k++) {
                acc0 = fmaf(t3[k], sW4[k * 3 + 0], acc0);
                acc1 = fmaf(t3[k], sW4[k * 3 + 1], acc1);
                acc2 = fmaf(t3[k], sW4[k * 3 + 2], acc2);
            }
            o0 = acc0; o1 = acc1; o2 = acc2;
        }

        if (out_sel == 2) {                  // final layer -> packed N x 3 output
            d_out[3 * i + 0] = o0;
            d_out[3 * i + 1] = o1;
            d_out[3 * i + 2] = o2;
        } else {
            float4* xo = out_sel ? g_xb : g_xa;
            xo[i] = make_float4(o0, o1, o2, 0.0f);
        }
    }
}

// ---------------------------------------------------------------------------
// kernel_launch
// ---------------------------------------------------------------------------
extern "C" void kernel_launch(void* const* d_in, const int* in_sizes, int n_in,
                              void* d_out, int out_size) {
    const float* node_embeds = (const float*)d_in[0];
    const float* edge_embeds = (const float*)d_in[1];
    const int*   edge_index  = (const int*)d_in[2];
    const float* W1 = (const float*)d_in[3];
    const float* b1 = (const float*)d_in[4];
    const float* W2 = (const float*)d_in[5];
    const float* b2 = (const float*)d_in[6];
    const float* W3 = (const float*)d_in[7];
    const float* b3 = (const float*)d_in[8];
    const float* W4 = (const float*)d_in[9];
    const float* b4 = (const float*)d_in[10];
    float* out = (float*)d_out;

    const int EB = 256;
    const int hgrid = (EE / 2 + EB - 1) / EB;    // 2 edges/thread (also covers NN conv)
    const int lgrid = (NN + 7) / 8;              // 8 nodes (warps) per 256-thread block

    hist_kernel<<<hgrid, EB>>>(edge_index, node_embeds);
    scan_kernel<<<1, SCAN_T>>>();
    scatter_kernel<<<hgrid, EB>>>(edge_embeds, edge_index);

    // layer 0: g_xa -> g_xb ; layer 1: g_xb -> g_xa ; layer 2: g_xa -> d_out
    layer_kernel<<<lgrid, 256>>>(0, 1, out, W1, b1, W2, b2, W3, b3, W4, b4, 0);
    layer_kernel<<<lgrid, 256>>>(1, 0, out, W1, b1, W2, b2, W3, b3, W4, b4, 1);
    layer_kernel<<<lgrid, 256>>>(0, 2, out, W1, b1, W2, b2, W3, b3, W4, b4, 2);
}

// round 7
// speedup vs baseline: 1.3566x; 1.0117x over previous
#include <cuda_runtime.h>

#define NN 10000
#define EE 640000           // == 2500 * 256 exactly (edge kernel has no ragged tail)
#define TRI_N 49995000      // N*(N-1)/2
#define NEG_SLOPE 0.01f
#define SCAN_T 1024
#define CHUNK 10            // ceil(NN / SCAN_T)

// ---------------------------------------------------------------------------
// Scratch (device globals; BSS zero-initialized at load, so g_cnt/g_agg start 0)
// ---------------------------------------------------------------------------
__device__ int    g_cnt[NN];       // per-target running counters
__device__ int    g_row[NN + 1];   // CSR row pointers
__device__ float4 g_edge[EE];      // CSR edges: (ef0, ef1, ef2, pack(src | tgt<<14))
__device__ float4 g_agg[NN];       // per-layer aggregation (atomic per component)
__device__ float4 g_xa[NN];        // x ping (padded to 16B for 1-load gather)
__device__ float4 g_xb[NN];        // x pong

// ---------------------------------------------------------------------------
// 1) Histogram of targets (2 edges/thread via int4) + node_embeds -> float4
//    + zero g_agg.
// ---------------------------------------------------------------------------
__global__ void __launch_bounds__(256) hist_kernel(const int* __restrict__ edge_index,
                                                   const float* __restrict__ node_embeds) {
    int t = blockIdx.x * blockDim.x + threadIdx.x;

    if (t < NN) {
        const float* p = node_embeds + 3 * t;
        g_xa[t]  = make_float4(p[0], p[1], p[2], 0.0f);
        g_agg[t] = make_float4(0.0f, 0.0f, 0.0f, 0.0f);
    }

    if (2 * t >= EE) return;
    int4 q = ((const int4*)edge_index)[t];   // edges 2t and 2t+1
    atomicAdd(&g_cnt[q.y], 1);
    atomicAdd(&g_cnt[q.w], 1);
}

// ---------------------------------------------------------------------------
// 2) Exclusive prefix scan over the 10k counters -> g_row; zero counters
// ---------------------------------------------------------------------------
__global__ void scan_kernel() {
    __shared__ int sp[SCAN_T];
    int tid = threadIdx.x;
    int beg = tid * CHUNK;
    int end = min(beg + CHUNK, NN);

    int local[CHUNK];
    int sum = 0;
    for (int k = beg; k < end; k++) {
        int v = g_cnt[k];
        local[k - beg] = v;
        sum += v;
    }
    sp[tid] = sum;
    __syncthreads();

    for (int off = 1; off < SCAN_T; off <<= 1) {
        int v = (tid >= off) ? sp[tid - off] : 0;
        __syncthreads();
        sp[tid] += v;
        __syncthreads();
    }

    int run = (tid == 0) ? 0 : sp[tid - 1];  // exclusive
    for (int k = beg; k < end; k++) {
        g_row[k] = run;
        run += local[k - beg];
        g_cnt[k] = 0;                        // ready for scatter
    }
    if (tid == 0) g_row[NN] = EE;
}

// ---------------------------------------------------------------------------
// 3) Scatter: 2 edges/thread. Random gather from the 600MB triangular array,
//    place edges in CSR order with src|tgt packed into word 3.
// ---------------------------------------------------------------------------
__global__ void __launch_bounds__(256) scatter_kernel(const float* __restrict__ edge_embeds,
                                                      const int* __restrict__ edge_index) {
    int t = blockIdx.x * blockDim.x + threadIdx.x;
    if (2 * t >= EE) return;

    int4 q = ((const int4*)edge_index)[t];
    int sA = q.x, tA = q.y;
    int sB = q.z, tB = q.w;

    int aA = min(sA, tA), bA = max(sA, tA);
    int aB = min(sB, tB), bB = max(sB, tB);
    int triA = aA * NN - (aA * (aA + 3)) / 2 + bA - 1;
    int triB = aB * NN - (aB * (aB + 3)) / 2 + bB - 1;
    if (triA < 0) triA += TRI_N;             // JAX wraps index -1 (a==b==0)
    if (triB < 0) triB += TRI_N;

    const float* pA = edge_embeds + (long long)triA * 3;
    const float* pB = edge_embeds + (long long)triB * 3;
    // 6 independent loads in flight
    float fA0 = __ldg(pA + 0), fA1 = __ldg(pA + 1), fA2 = __ldg(pA + 2);
    float fB0 = __ldg(pB + 0), fB1 = __ldg(pB + 1), fB2 = __ldg(pB + 2);

    int posA = g_row[tA] + atomicAdd(&g_cnt[tA], 1);
    int posB = g_row[tB] + atomicAdd(&g_cnt[tB], 1);
    int pkA = sA | (tA << 14);               // both < 2^14
    int pkB = sB | (tB << 14);
    __stcg(&g_edge[posA], make_float4(fA0, fA1, fA2, __int_as_float(pkA)));
    __stcg(&g_edge[posB], make_float4(fB0, fB1, fB2, __int_as_float(pkB)));
}

// ---------------------------------------------------------------------------
// 4a) Edge pass (per layer): one thread per edge. msg = relu(x[src]+ef),
//     segmented warp suffix-reduction over the sorted tgt runs, then one
//     global atomicAdd per (segment-head, component).
// ---------------------------------------------------------------------------
__global__ void __launch_bounds__(256) edge_kernel(int in_sel) {
    int e = blockIdx.x * blockDim.x + threadIdx.x;   // EE is a multiple of 256
    int lane = threadIdx.x & 31;

    const float4* __restrict__ x = in_sel ? g_xb : g_xa;

    float4 v = __ldg(&g_edge[e]);
    int pk = __float_as_int(v.w);
    int s = pk & 0x3FFF;
    int t = pk >> 14;

    float4 xs = __ldg(&x[s]);
    float m0 = fmaxf(xs.x + v.x, 0.0f);
    float m1 = fmaxf(xs.y + v.y, 0.0f);
    float m2 = fmaxf(xs.z + v.z, 0.0f);

    // Segmented suffix reduction: after this, each segment-head lane holds
    // the sum of its run (t is non-decreasing within the warp).
#pragma unroll
    for (int off = 1; off < 32; off <<= 1) {
        float b0 = __shfl_down_sync(0xFFFFFFFF, m0, off);
        float b1 = __shfl_down_sync(0xFFFFFFFF, m1, off);
        float b2 = __shfl_down_sync(0xFFFFFFFF, m2, off);
        int   tn = __shfl_down_sync(0xFFFFFFFF, t,  off);
        if (lane + off < 32 && tn == t) { m0 += b0; m1 += b1; m2 += b2; }
    }
    int tp = __shfl_up_sync(0xFFFFFFFF, t, 1);
    if (lane == 0 || tp != t) {
        float* agg = (float*)&g_agg[t];
        atomicAdd(agg + 0, m0);
        atomicAdd(agg + 1, m1);
        atomicAdd(agg + 2, m2);
    }
}

// ---------------------------------------------------------------------------
// 4b) Node pass (per layer): one thread per node, full-ILP MLP.
//     Re-zeros g_agg for the next layer / replay; layer 0 re-zeros g_cnt.
// ---------------------------------------------------------------------------
__device__ __forceinline__ float leaky(float v) {
    return v >= 0.0f ? v : NEG_SLOPE * v;
}

__global__ void __launch_bounds__(256) node_kernel(
                             int in_sel, int out_sel,
                             float* __restrict__ d_out,
                             const float* __restrict__ W1, const float* __restrict__ b1,
                             const float* __restrict__ W2, const float* __restrict__ b2,
                             const float* __restrict__ W3, const float* __restrict__ b3,
                             const float* __restrict__ W4, const float* __restrict__ b4,
                             int layer) {
    __shared__ float sW1[36], sb1[6], sW2[36], sb2[6], sW3[18], sb3[3], sW4[9], sb4[3];
    int tid = threadIdx.x;
    if (tid < 36) { sW1[tid] = W1[layer * 36 + tid]; sW2[tid] = W2[layer * 36 + tid]; }
    if (tid < 18) { sW3[tid] = W3[layer * 18 + tid]; }
    if (tid < 9)  { sW4[tid] = W4[layer * 9 + tid]; }
    if (tid < 6)  { sb1[tid] = b1[layer * 6 + tid]; sb2[tid] = b2[layer * 6 + tid]; }
    if (tid < 3)  { sb3[tid] = b3[layer * 3 + tid]; sb4[tid] = b4[layer * 3 + tid]; }
    __syncthreads();

    int i = blockIdx.x * blockDim.x + tid;
    if (i >= NN) return;

    const float4* __restrict__ x = in_sel ? g_xb : g_xa;

    float4 ag = g_agg[i];
    g_agg[i] = make_float4(0.0f, 0.0f, 0.0f, 0.0f);   // ready for next layer/replay
    if (layer == 0) g_cnt[i] = 0;                     // ready for next replay

    float4 xi = x[i];
    float h[6];
    h[0] = ag.x; h[1] = ag.y; h[2] = ag.z;
    h[3] = xi.x; h[4] = xi.y; h[5] = xi.z;

    float t1[6], t2[6], t3[3];
#pragma unroll
    for (int j = 0; j < 6; j++) {
        float acc = sb1[j];
#pragma unroll
        for (int k = 0; k < 6; k++) acc = fmaf(h[k], sW1[k * 6 + j], acc);
        t1[j] = leaky(acc);
    }
#pragma unroll
    for (int j = 0; j < 6; j++) {
        float acc = sb2[j];
#pragma unroll
        for (int k = 0; k < 6; k++) acc = fmaf(t1[k], sW2[k * 6 + j], acc);
        t2[j] = leaky(acc);
    }
#pragma unroll
    for (int j = 0; j < 3; j++) {
        float acc = sb3[j];
#pragma unroll
        for (int k = 0; k < 6; k++) acc = fmaf(t2[k], sW3[k * 3 + j], acc);
        t3[j] = leaky(acc);
    }
    float o0 = sb4[0], o1 = sb4[1], o2 = sb4[2];
#pragma unroll
    for (int k = 0; k < 3; k++) {
        o0 = fmaf(t3[k], sW4[k * 3 + 0], o0);
        o1 = fmaf(t3[k], sW4[k * 3 + 1], o1);
        o2 = fmaf(t3[k], sW4[k * 3 + 2], o2);
    }

    if (out_sel == 2) {                  // final layer -> packed N x 3 output
        d_out[3 * i + 0] = o0;
        d_out[3 * i + 1] = o1;
        d_out[3 * i + 2] = o2;
    } else {
        float4* xo = out_sel ? g_xb : g_xa;
        xo[i] = make_float4(o0, o1, o2, 0.0f);
    }
}

// ---------------------------------------------------------------------------
// kernel_launch
// ---------------------------------------------------------------------------
extern "C" void kernel_launch(void* const* d_in, const int* in_sizes, int n_in,
                              void* d_out, int out_size) {
    const float* node_embeds = (const float*)d_in[0];
    const float* edge_embeds = (const float*)d_in[1];
    const int*   edge_index  = (const int*)d_in[2];
    const float* W1 = (const float*)d_in[3];
    const float* b1 = (const float*)d_in[4];
    const float* W2 = (const float*)d_in[5];
    const float* b2 = (const float*)d_in[6];
    const float* W3 = (const float*)d_in[7];
    const float* b3 = (const float*)d_in[8];
    const float* W4 = (const float*)d_in[9];
    const float* b4 = (const float*)d_in[10];
    float* out = (float*)d_out;

    const int EB = 256;
    const int hgrid = (EE / 2 + EB - 1) / EB;    // 2 edges/thread (covers NN too)
    const int egrid = EE / EB;                   // exact: 2500
    const int ngrid = (NN + EB - 1) / EB;

    hist_kernel<<<hgrid, EB>>>(edge_index, node_embeds);
    scan_kernel<<<1, SCAN_T>>>();
    scatter_kernel<<<hgrid, EB>>>(edge_embeds, edge_index);

    // layer 0: g_xa -> g_xb ; layer 1: g_xb -> g_xa ; layer 2: g_xa -> d_out
    edge_kernel<<<egrid, EB>>>(0);
    node_kernel<<<ngrid, EB>>>(0, 1, out, W1, b1, W2, b2, W3, b3, W4, b4, 0);
    edge_kernel<<<egrid, EB>>>(1);
    node_kernel<<<ngrid, EB>>>(1, 0, out, W1, b1, W2, b2, W3, b3, W4, b4, 1);
    edge_kernel<<<egrid, EB>>>(0);
    node_kernel<<<ngrid, EB>>>(0, 2, out, W1, b1, W2, b2, W3, b3, W4, b4, 2);
}